// round 2
// baseline (speedup 1.0000x reference)
#include <cuda_runtime.h>

#define SLEN 2048
#define NH   16
#define HD   64
#define QT   64
#define KT   64
#define LDP  68
#define LOG2E 1.4426950408889634f

// Scratch (allocation-free rule: __device__ globals)
__device__ float g_KcT[NH * HD * SLEN];   // compacted K, transposed: [h][d][j]
__device__ float g_Vc [NH * SLEN * HD];   // compacted V, row-major:  [h][j][d]
__device__ float g_posf[SLEN];            // (pos - (S-1)) for valid j, -1e30 for pad
__device__ int   g_pos [SLEN];
__device__ int   g_nvalid;

// ---------------------------------------------------------------------------
// Kernel 1: compact the boolean key mask into a position list (block scan).
// The mask's on-device layout is detected at runtime: the harness may pass
// numpy bool as either 1-byte bool or widened int32. Reading the first 2048
// BYTES is in-bounds under both interpretations; a random 0/1 byte-mask has
// ~768 nonzero bytes at indices i%4!=0, while an int32 0/1 buffer has none.
// ---------------------------------------------------------------------------
__global__ void compact_kernel(const unsigned char* __restrict__ mask8) {
    __shared__ int cnt[256];
    __shared__ int s_n;
    int tid  = threadIdx.x;
    int base = tid * 8;

    // Layout detection (first 2048 bytes, safe either way)
    int probe = 0;
#pragma unroll
    for (int i = 0; i < 8; i++) {
        int p = base + i;
        if ((p & 3) != 0 && mask8[p] != 0) probe = 1;
    }
    int isU8 = __syncthreads_or(probe);

    const int* mask32 = (const int*)mask8;
    int v[8], c = 0;
#pragma unroll
    for (int i = 0; i < 8; i++) {
        int e = base + i;
        int val = isU8 ? (int)(mask8[e] != 0) : (int)(mask32[e] != 0);
        v[i] = val;
        c += val;
    }
    cnt[tid] = c;
    __syncthreads();
    for (int off = 1; off < 256; off <<= 1) {
        int t = (tid >= off) ? cnt[tid - off] : 0;
        __syncthreads();
        cnt[tid] += t;
        __syncthreads();
    }
    int idx = cnt[tid] - c;  // exclusive prefix
#pragma unroll
    for (int i = 0; i < 8; i++) {
        if (v[i]) {
            g_pos [idx] = base + i;
            g_posf[idx] = (float)(base + i - (SLEN - 1));
            idx++;
        }
    }
    if (tid == 255) { s_n = cnt[255]; g_nvalid = cnt[255]; }
    __syncthreads();
    for (int j = s_n + tid; j < SLEN; j += 256) g_posf[j] = -1.0e30f;
}

// ---------------------------------------------------------------------------
// Kernel 2: gather valid K rows into transposed layout [h][d][j] and valid V
// rows into [h][j][d]. Pad rows (j >= n_valid) are zero-filled.
// ---------------------------------------------------------------------------
__global__ void scatter_kernel(const float* __restrict__ K, const float* __restrict__ V) {
    int h   = blockIdx.y;
    int jin = threadIdx.x & 15;
    int d4  = threadIdx.x >> 4;              // 0..15
    int j   = blockIdx.x * 16 + jin;         // 0..2047
    int n   = g_nvalid;
    float4 kk = make_float4(0.f, 0.f, 0.f, 0.f);
    float4 vv = kk;
    if (j < n) {
        int src = g_pos[j];
        kk = *(const float4*)(K + ((size_t)h * SLEN + src) * HD + d4 * 4);
        vv = *(const float4*)(V + ((size_t)h * SLEN + src) * HD + d4 * 4);
    }
    float* kt = g_KcT + (size_t)h * HD * SLEN;
    kt[(4 * d4 + 0) * SLEN + j] = kk.x;      // lanes = consecutive j -> coalesced
    kt[(4 * d4 + 1) * SLEN + j] = kk.y;
    kt[(4 * d4 + 2) * SLEN + j] = kk.z;
    kt[(4 * d4 + 3) * SLEN + j] = kk.w;
    *(float4*)(g_Vc + ((size_t)h * SLEN + j) * HD + d4 * 4) = vv;
}

// ---------------------------------------------------------------------------
// Kernel 3: flash attention over compacted keys.
// Grid (S/QT, H), 256 threads = 16(ty:q-groups) x 16(tx:k/d-groups),
// 4x4 register tiles for both S and O.
// ---------------------------------------------------------------------------
__global__ __launch_bounds__(256) void attn_kernel(const float* __restrict__ Q,
                                                   float* __restrict__ Out) {
    extern __shared__ float sm[];
    float* Qs  = sm;                 // [d][q]  (transposed), LDP-padded
    float* Ks  = Qs + HD * LDP;      // [d][k]  (transposed)
    float* Vs  = Ks + HD * LDP;      // [k][d]
    float* Ps  = Vs + KT * LDP;      // [q][k]
    float* djs = Ps + QT * LDP;      // [KT]

    int tid = threadIdx.x;
    int h   = blockIdx.y;
    int q0  = blockIdx.x * QT;
    int ty  = tid >> 4, tx = tid & 15;
    float slope = exp2f(-0.5f * (float)(h + 1));   // ALiBi slope, H=16 power of 2

    // Load Q tile transposed (once per CTA; scalar STS conflicts amortized)
    const float* Qg = Q + ((size_t)h * SLEN + q0) * HD;
#pragma unroll
    for (int idx = tid; idx < QT * 16; idx += 256) {
        int q = idx >> 4, w = idx & 15;
        float4 t = *(const float4*)(Qg + q * HD + w * 4);
        Qs[(4 * w + 0) * LDP + q] = t.x;
        Qs[(4 * w + 1) * LDP + q] = t.y;
        Qs[(4 * w + 2) * LDP + q] = t.z;
        Qs[(4 * w + 3) * LDP + q] = t.w;
    }

    float o[4][4] = {};
    float m[4], l[4];
#pragma unroll
    for (int r = 0; r < 4; r++) { m[r] = __int_as_float(0xff800000); l[r] = 0.f; }

    int n      = g_nvalid;
    int ntiles = (n + KT - 1) >> 6;
    const float* KgT = g_KcT + (size_t)h * HD * SLEN;
    const float* Vg  = g_Vc  + (size_t)h * SLEN * HD;

    for (int t = 0; t < ntiles; ++t) {
        int k0 = t * KT;
        __syncthreads();   // previous tile fully consumed before overwrite
        // Load K^T tile (already transposed globally -> float4, conflict-free)
        // and V tile (row index idx>>4 doubles as d for K and k for V).
#pragma unroll
        for (int idx = tid; idx < HD * 16; idx += 256) {
            int row = idx >> 4, c4 = idx & 15;
            float4 kk = *(const float4*)(KgT + row * SLEN + k0 + 4 * c4);
            *(float4*)&Ks[row * LDP + 4 * c4] = kk;
            float4 vv = *(const float4*)(Vg + (size_t)(k0 + row) * HD + 4 * c4);
            *(float4*)&Vs[row * LDP + 4 * c4] = vv;
        }
        if (tid < KT) djs[tid] = g_posf[k0 + tid];
        __syncthreads();

        // S = (Q K^T) * scale + slope * (pos - (S-1))
        float s[4][4] = {};
#pragma unroll 8
        for (int d = 0; d < HD; ++d) {
            float4 a = *(const float4*)&Qs[d * LDP + 4 * ty];
            float4 b = *(const float4*)&Ks[d * LDP + 4 * tx];
            s[0][0] += a.x * b.x; s[0][1] += a.x * b.y; s[0][2] += a.x * b.z; s[0][3] += a.x * b.w;
            s[1][0] += a.y * b.x; s[1][1] += a.y * b.y; s[1][2] += a.y * b.z; s[1][3] += a.y * b.w;
            s[2][0] += a.z * b.x; s[2][1] += a.z * b.y; s[2][2] += a.z * b.z; s[2][3] += a.z * b.w;
            s[3][0] += a.w * b.x; s[3][1] += a.w * b.y; s[3][2] += a.w * b.z; s[3][3] += a.w * b.w;
        }
        float bj[4];
#pragma unroll
        for (int c = 0; c < 4; c++) bj[c] = slope * djs[4 * tx + c];
#pragma unroll
        for (int r = 0; r < 4; r++)
#pragma unroll
            for (int c = 0; c < 4; c++) s[r][c] = s[r][c] * 0.125f + bj[c];

        // Online softmax; rows live entirely within 16-lane tx-groups.
#pragma unroll
        for (int r = 0; r < 4; r++) {
            float tm = fmaxf(fmaxf(s[r][0], s[r][1]), fmaxf(s[r][2], s[r][3]));
            tm = fmaxf(tm, __shfl_xor_sync(0xffffffffu, tm, 8));
            tm = fmaxf(tm, __shfl_xor_sync(0xffffffffu, tm, 4));
            tm = fmaxf(tm, __shfl_xor_sync(0xffffffffu, tm, 2));
            tm = fmaxf(tm, __shfl_xor_sync(0xffffffffu, tm, 1));
            float mn = fmaxf(m[r], tm);
            float al = exp2f((m[r] - mn) * LOG2E);
            m[r] = mn;
            s[r][0] = exp2f((s[r][0] - mn) * LOG2E);
            s[r][1] = exp2f((s[r][1] - mn) * LOG2E);
            s[r][2] = exp2f((s[r][2] - mn) * LOG2E);
            s[r][3] = exp2f((s[r][3] - mn) * LOG2E);
            float rs = (s[r][0] + s[r][1]) + (s[r][2] + s[r][3]);
            rs += __shfl_xor_sync(0xffffffffu, rs, 8);
            rs += __shfl_xor_sync(0xffffffffu, rs, 4);
            rs += __shfl_xor_sync(0xffffffffu, rs, 2);
            rs += __shfl_xor_sync(0xffffffffu, rs, 1);
            l[r] = l[r] * al + rs;
            o[r][0] *= al; o[r][1] *= al; o[r][2] *= al; o[r][3] *= al;
            *(float4*)&Ps[(4 * ty + r) * LDP + 4 * tx] =
                make_float4(s[r][0], s[r][1], s[r][2], s[r][3]);
        }
        __syncthreads();

        // O += P V  (k blocked by 4 so P reads are float4 broadcasts)
#pragma unroll 4
        for (int k4 = 0; k4 < KT / 4; ++k4) {
            float4 p0 = *(const float4*)&Ps[(4 * ty + 0) * LDP + 4 * k4];
            float4 p1 = *(const float4*)&Ps[(4 * ty + 1) * LDP + 4 * k4];
            float4 p2 = *(const float4*)&Ps[(4 * ty + 2) * LDP + 4 * k4];
            float4 p3 = *(const float4*)&Ps[(4 * ty + 3) * LDP + 4 * k4];
            float pa[4][4] = {{p0.x, p0.y, p0.z, p0.w},
                              {p1.x, p1.y, p1.z, p1.w},
                              {p2.x, p2.y, p2.z, p2.w},
                              {p3.x, p3.y, p3.z, p3.w}};
#pragma unroll
            for (int i = 0; i < 4; ++i) {
                float4 v = *(const float4*)&Vs[(4 * k4 + i) * LDP + 4 * tx];
                o[0][0] += pa[0][i] * v.x; o[0][1] += pa[0][i] * v.y; o[0][2] += pa[0][i] * v.z; o[0][3] += pa[0][i] * v.w;
                o[1][0] += pa[1][i] * v.x; o[1][1] += pa[1][i] * v.y; o[1][2] += pa[1][i] * v.z; o[1][3] += pa[1][i] * v.w;
                o[2][0] += pa[2][i] * v.x; o[2][1] += pa[2][i] * v.y; o[2][2] += pa[2][i] * v.z; o[2][3] += pa[2][i] * v.w;
                o[3][0] += pa[3][i] * v.x; o[3][1] += pa[3][i] * v.y; o[3][2] += pa[3][i] * v.z; o[3][3] += pa[3][i] * v.w;
            }
        }
    }

    float* Og = Out + ((size_t)h * SLEN + q0) * HD;
#pragma unroll
    for (int r = 0; r < 4; r++) {
        float inv = 1.0f / l[r];
        *(float4*)(Og + (4 * ty + r) * HD + 4 * tx) =
            make_float4(o[r][0] * inv, o[r][1] * inv, o[r][2] * inv, o[r][3] * inv);
    }
}

// ---------------------------------------------------------------------------
extern "C" void kernel_launch(void* const* d_in, const int* in_sizes, int n_in,
                              void* d_out, int out_size) {
    const float*         Q    = (const float*)d_in[0];
    const float*         K    = (const float*)d_in[1];
    const float*         V    = (const float*)d_in[2];
    const unsigned char* mask = (const unsigned char*)d_in[3];
    float*               out  = (float*)d_out;

    const int SMEM_BYTES = (3 * HD * LDP + QT * LDP + KT) * (int)sizeof(float); // 69888
    cudaFuncSetAttribute(attn_kernel, cudaFuncAttributeMaxDynamicSharedMemorySize, SMEM_BYTES);

    compact_kernel<<<1, 256>>>(mask);
    dim3 gs(SLEN / 16, NH);
    scatter_kernel<<<gs, 256>>>(K, V);
    dim3 ga(SLEN / QT, NH);
    attn_kernel<<<ga, 256, SMEM_BYTES>>>(Q, out);
}